// round 12
// baseline (speedup 1.0000x reference)
#include <cuda_runtime.h>
#include <cuda_bf16.h>
#include <cuda_fp16.h>
#include <mma.h>
#include <cstdint>

using namespace nvcuda;

#define BSZ 16
#define NN  96
#define HD  128
#define BN  (BSZ*NN)

#define LDAB 136
#define LDO  132
#define LDS_STG 20

// ---- edge kernel smem layout (80.1 KB -> 2 blocks/SM) ----
#define W2HI  0
#define MHI   34816
#define STGO  60928
#define RSO   76288
#define DSO   76672
#define EMO   77056
#define B2O   77440
#define W3O   77952
#define PARTO 78464
#define PXYO  80000
#define SMEMB 80064

// ---- k_hihjW smem (fp16 A single) ----
#define H_XH  0            // 32*136*2 = 8704
#define H_WH  8704         // 34816
#define H_WL  43520        // 34816
#define H_BI  78336        // 8448
#define H_SMEM 86784

// ---- k_nodeW smem (fp16 A single, no alias) ----
#define N_XH  0            // 8704
#define N_AH  8704         // 8704
#define N_WH  17408        // 34816
#define N_WL  52224        // 34816
#define N_SO  87040        // 16896
#define N_BI  103936       // 8448
#define N_SMEM 112384

// ---------------- scratch ----------------
__device__ float g_h  [BN*HD];
__device__ float g_Hi [BN*HD];
__device__ float g_Hj [BN*HD];
__device__ __half g_Hj16[BN*HD];
__device__ float g_agg[BN*HD];
__device__ float g_x  [BN*3];
__device__ float g_x0 [BN*3];
__device__ float g_rad[BN*NN];
__device__ float g_d0 [BN*NN];
__device__ float g_cd [BN*NN*3];

// ---------------- pre-split weights (fp16 hi/lo) ----------------
#define N_WE1 (12*256*128)
#define N_W2  (12*128*128)
#define N_WN1 (8*256*128)
#define N_WN2 (8*128*128)
__device__ __half s_We1h[N_WE1], s_We1l[N_WE1];
__device__ __half s_W2h [N_W2];
__device__ __half s_Wn1h[N_WN1], s_Wn1l[N_WN1];
__device__ __half s_Wn2h[N_WN2], s_Wn2l[N_WN2];

__device__ __forceinline__ float silu_f(float x){
    float e = __expf(-x);
    return __fdividef(x, 1.0f + e);
}
__device__ __forceinline__ half2 silu_h2(half2 x){
    half2 e = h2exp(__hneg2(x));
    half2 d = __hadd2(__float2half2_rn(1.0f), e);
    return __hmul2(x, h2rcp(d));
}
__device__ __forceinline__ void split_fp16(float v, __half &h, __half &l){
    h = __float2half_rn(v);
    l = __float2half_rn(v - __half2float(h));
}

// ---------------- one-time weight split ----------------
__global__ void k_split(const float* __restrict__ gWe1, const float* __restrict__ eWc1,
                        const float* __restrict__ gWe2, const float* __restrict__ eWc2,
                        const float* __restrict__ gWn1, const float* __restrict__ gWn2){
    int idx = blockIdx.x*blockDim.x + threadIdx.x;
    const int T0 = N_WE1, T1 = T0 + N_W2, T2 = T1 + N_WN1, T3 = T2 + N_WN2;
    if (idx >= T3) return;
    if (idx < T0){
        int g = idx / (256*128), rem = idx % (256*128);
        float v = (g < 8) ? gWe1[(size_t)g*258*128 + rem] : eWc1[(size_t)(g-8)*258*128 + rem];
        __half h, l; split_fp16(v, h, l); s_We1h[idx] = h; s_We1l[idx] = l;
    } else if (idx < T1){
        int i = idx - T0;
        int g = i / (128*128), rem = i % (128*128);
        float v = (g < 8) ? gWe2[(size_t)g*128*128 + rem] : eWc2[(size_t)(g-8)*128*128 + rem];
        s_W2h[i] = __float2half_rn(v);
    } else if (idx < T2){
        int i = idx - T1;
        __half h, l; split_fp16(gWn1[i], h, l); s_Wn1h[i] = h; s_Wn1l[i] = l;
    } else {
        int i = idx - T2;
        __half h, l; split_fp16(gWn2[i], h, l); s_Wn2h[i] = h; s_Wn2l[i] = l;
    }
}

// ---------------- init ----------------
__global__ void k_init(const float* __restrict__ xh, const float* __restrict__ t,
                       const float* __restrict__ nm, const float* __restrict__ W_emb,
                       const float* __restrict__ b_emb){
    int n = blockIdx.x; int c = threadIdx.x;
    __shared__ float fs[8];
    float mask = nm[n];
    if (c < 6) fs[c] = xh[n*9 + 3 + c] * mask;
    if (c == 6) fs[6] = t[0];
    if (c < 3){ float v = xh[n*9 + c] * mask; g_x0[n*3+c] = v; g_x[n*3+c] = v; }
    __syncthreads();
    float a = b_emb[c];
    #pragma unroll
    for (int f=0; f<7; f++) a += fs[f] * W_emb[f*HD + c];
    g_h[n*HD + c] = a;
}

// ---------------- radial ----------------
__global__ void k_radial(int mode){
    int bi = blockIdx.x; int j = threadIdx.x;
    int b = bi / NN;
    const float* X = mode ? g_x : g_x0;
    float xi0 = X[bi*3+0], xi1 = X[bi*3+1], xi2 = X[bi*3+2];
    int nj = b*NN + j;
    float dx = xi0 - X[nj*3+0];
    float dy = xi1 - X[nj*3+1];
    float dz = xi2 - X[nj*3+2];
    float r = dx*dx + dy*dy + dz*dz;
    if (mode){
        g_rad[bi*NN + j] = r;
        float inv = rsqrtf(r + 1e-8f);
        int e = (bi*NN + j)*3;
        g_cd[e+0] = dx*inv; g_cd[e+1] = dy*inv; g_cd[e+2] = dz*inv;
    } else {
        g_d0[bi*NN + j] = r;
    }
}

// copy a 128x128 2-byte matrix into padded smem, vectorized
__device__ __forceinline__ void load_w_tile2(void* dst, const void* src, int tid, int nthr){
    const uint4* s = (const uint4*)src;
    char* d = (char*)dst;
    for (int i = tid; i < 128*128/8; i += nthr){
        int r = i >> 4, c8 = i & 15;
        *reinterpret_cast<uint4*>(d + (r*LDAB + c8*8)*2) = s[i];
    }
}

// ---------------- Hi/Hj via WMMA (A fp16 single, W fp16 hi/lo, 2-pass) ----------------
__global__ void __launch_bounds__(256,2) k_hihjW(const float* __restrict__ b1, int g){
    extern __shared__ char sm[];
    __half* xh = (__half*)(sm + H_XH);
    __half* wh = (__half*)(sm + H_WH);
    __half* wl = (__half*)(sm + H_WL);
    float* bias = (float*)(sm + H_BI);

    int tid = threadIdx.x;
    int wid = tid >> 5;
    int mw  = wid >> 2;
    int nw  = wid & 3;
    int half_  = blockIdx.x & 1;
    int rows0 = (blockIdx.x >> 1) * 32;

    for (int idx = tid; idx < 32*128; idx += 256){
        int r = idx >> 7, k = idx & 127;
        xh[r*LDAB + k] = __float2half_rn(g_h[(rows0+r)*HD + k]);
    }
    load_w_tile2(wh, s_We1h + ((size_t)g*256 + half_*128)*128, tid, 256);
    load_w_tile2(wl, s_We1l + ((size_t)g*256 + half_*128)*128, tid, 256);
    for (int idx = tid; idx < 16*132; idx += 256){
        int cc = idx % 132;
        bias[idx] = (half_ == 0 && cc < 128) ? b1[cc] : 0.f;
    }
    __syncthreads();

    wmma::fragment<wmma::accumulator,16,16,16,float> acc[2];
    #pragma unroll
    for (int ni=0; ni<2; ni++)
        wmma::load_matrix_sync(acc[ni], bias + nw*32 + ni*16, 132, wmma::mem_row_major);
    #pragma unroll
    for (int s=0; s<8; s++){
        wmma::fragment<wmma::matrix_a,16,16,16,__half,wmma::row_major> fa;
        wmma::fragment<wmma::matrix_b,16,16,16,__half,wmma::row_major> fbh[2], fbl[2];
        wmma::load_matrix_sync(fa, xh + (mw*16)*LDAB + s*16, LDAB);
        #pragma unroll
        for (int ni=0; ni<2; ni++){
            wmma::load_matrix_sync(fbh[ni], wh + s*16*LDAB + nw*32 + ni*16, LDAB);
            wmma::load_matrix_sync(fbl[ni], wl + s*16*LDAB + nw*32 + ni*16, LDAB);
        }
        #pragma unroll
        for (int ni=0; ni<2; ni++){
            wmma::mma_sync(acc[ni], fa, fbh[ni], acc[ni]);
            wmma::mma_sync(acc[ni], fa, fbl[ni], acc[ni]);
        }
    }
    float* dstbase = half_ ? g_Hj : g_Hi;
    #pragma unroll
    for (int ni=0; ni<2; ni++)
        wmma::store_matrix_sync(dstbase + (size_t)(rows0 + mw*16)*HD + nw*32 + ni*16,
                                acc[ni], HD, wmma::mem_row_major);
    if (half_ == 1){
        __syncthreads();   // all warps' global stores visible to block
        for (int idx = tid; idx < 32*128; idx += 256){
            int r = idx >> 7, cc = idx & 127;
            size_t o = (size_t)(rows0+r)*HD + cc;
            g_Hj16[o] = __float2half_rn(g_Hj[o]);
        }
    }
}

// ---------------- node MLP via WMMA (A fp16 single, W fp16 hi/lo, 2-pass) ----------------
__global__ void __launch_bounds__(256,2) k_nodeW(const float* __restrict__ bn1,
                       const float* __restrict__ bn2, const float* __restrict__ nm, int g){
    extern __shared__ char sm[];
    __half* xh = (__half*)(sm + N_XH);
    __half* ah_ = (__half*)(sm + N_AH);
    __half* wh = (__half*)(sm + N_WH);
    __half* wl = (__half*)(sm + N_WL);
    float* sout = (float*)(sm + N_SO);
    float* bias = (float*)(sm + N_BI);

    int tid = threadIdx.x;
    int wid = tid >> 5;
    int mw  = wid >> 2;
    int nw  = wid & 3;
    int rows0 = blockIdx.x * 32;

    for (int idx = tid; idx < 32*128; idx += 256){
        int r = idx >> 7, k = idx & 127;
        xh[r*LDAB + k]  = __float2half_rn(g_h[(rows0+r)*HD + k]);
        ah_[r*LDAB + k] = __float2half_rn(g_agg[(rows0+r)*HD + k]);
    }
    load_w_tile2(wh, s_Wn1h + (size_t)g*256*128, tid, 256);
    load_w_tile2(wl, s_Wn1l + (size_t)g*256*128, tid, 256);
    for (int idx = tid; idx < 16*132; idx += 256){
        int cc = idx % 132;
        bias[idx] = (cc < 128) ? bn1[cc] : 0.f;
    }
    __syncthreads();

    wmma::fragment<wmma::accumulator,16,16,16,float> acc[2];
    #pragma unroll
    for (int ni=0; ni<2; ni++)
        wmma::load_matrix_sync(acc[ni], bias + nw*32 + ni*16, 132, wmma::mem_row_major);

    #pragma unroll
    for (int s=0; s<8; s++){
        wmma::fragment<wmma::matrix_a,16,16,16,__half,wmma::row_major> fa;
        wmma::fragment<wmma::matrix_b,16,16,16,__half,wmma::row_major> fbh[2], fbl[2];
        wmma::load_matrix_sync(fa, xh + (mw*16)*LDAB + s*16, LDAB);
        #pragma unroll
        for (int ni=0; ni<2; ni++){
            wmma::load_matrix_sync(fbh[ni], wh + s*16*LDAB + nw*32 + ni*16, LDAB);
            wmma::load_matrix_sync(fbl[ni], wl + s*16*LDAB + nw*32 + ni*16, LDAB);
        }
        #pragma unroll
        for (int ni=0; ni<2; ni++){
            wmma::mma_sync(acc[ni], fa, fbh[ni], acc[ni]);
            wmma::mma_sync(acc[ni], fa, fbl[ni], acc[ni]);
        }
    }
    __syncthreads();
    load_w_tile2(wh, s_Wn1h + ((size_t)g*256 + 128)*128, tid, 256);
    load_w_tile2(wl, s_Wn1l + ((size_t)g*256 + 128)*128, tid, 256);
    __syncthreads();
    #pragma unroll
    for (int s=0; s<8; s++){
        wmma::fragment<wmma::matrix_a,16,16,16,__half,wmma::row_major> fa;
        wmma::fragment<wmma::matrix_b,16,16,16,__half,wmma::row_major> fbh[2], fbl[2];
        wmma::load_matrix_sync(fa, ah_ + (mw*16)*LDAB + s*16, LDAB);
        #pragma unroll
        for (int ni=0; ni<2; ni++){
            wmma::load_matrix_sync(fbh[ni], wh + s*16*LDAB + nw*32 + ni*16, LDAB);
            wmma::load_matrix_sync(fbl[ni], wl + s*16*LDAB + nw*32 + ni*16, LDAB);
        }
        #pragma unroll
        for (int ni=0; ni<2; ni++){
            wmma::mma_sync(acc[ni], fa, fbh[ni], acc[ni]);
            wmma::mma_sync(acc[ni], fa, fbl[ni], acc[ni]);
        }
    }
    #pragma unroll
    for (int ni=0; ni<2; ni++)
        wmma::store_matrix_sync(sout + (mw*16)*LDO + nw*32 + ni*16, acc[ni], LDO, wmma::mem_row_major);
    __syncthreads();

    // u = silu(sout) -> xh fp16; W = Wn2; bias = bn2
    for (int idx = tid; idx < 32*128; idx += 256){
        int r = idx >> 7, cc = idx & 127;
        xh[r*LDAB + cc] = __float2half_rn(silu_f(sout[r*LDO + cc]));
    }
    load_w_tile2(wh, s_Wn2h + (size_t)g*128*128, tid, 256);
    load_w_tile2(wl, s_Wn2l + (size_t)g*128*128, tid, 256);
    for (int idx = tid; idx < 16*132; idx += 256){
        int cc = idx % 132;
        bias[idx] = (cc < 128) ? bn2[cc] : 0.f;
    }
    __syncthreads();

    #pragma unroll
    for (int ni=0; ni<2; ni++)
        wmma::load_matrix_sync(acc[ni], bias + nw*32 + ni*16, 132, wmma::mem_row_major);
    #pragma unroll
    for (int s=0; s<8; s++){
        wmma::fragment<wmma::matrix_a,16,16,16,__half,wmma::row_major> fa;
        wmma::fragment<wmma::matrix_b,16,16,16,__half,wmma::row_major> fbh[2], fbl[2];
        wmma::load_matrix_sync(fa, xh + (mw*16)*LDAB + s*16, LDAB);
        #pragma unroll
        for (int ni=0; ni<2; ni++){
            wmma::load_matrix_sync(fbh[ni], wh + s*16*LDAB + nw*32 + ni*16, LDAB);
            wmma::load_matrix_sync(fbl[ni], wl + s*16*LDAB + nw*32 + ni*16, LDAB);
        }
        #pragma unroll
        for (int ni=0; ni<2; ni++){
            wmma::mma_sync(acc[ni], fa, fbh[ni], acc[ni]);
            wmma::mma_sync(acc[ni], fa, fbl[ni], acc[ni]);
        }
    }
    __syncthreads();
    #pragma unroll
    for (int ni=0; ni<2; ni++)
        wmma::store_matrix_sync(sout + (mw*16)*LDO + nw*32 + ni*16, acc[ni], LDO, wmma::mem_row_major);
    __syncthreads();

    for (int idx = tid; idx < 32*128; idx += 256){
        int r = idx >> 7, cc = idx & 127;
        int n = rows0 + r;
        g_h[n*HD + cc] = (g_h[n*HD + cc] + sout[r*LDO + cc]) * nm[n];
    }
}

// ---------------- WMMA edge MLP: fp16 W2, fp16 Hj cache, paired-channel stage-1 ----------------
template<int COORD>
__global__ void __launch_bounds__(384,2) k_edgeW(const float* __restrict__ W1,
        const float* __restrict__ b2, const float* __restrict__ w3,
        const float* __restrict__ em, const float* __restrict__ nm, int widx){
    extern __shared__ char sm[];
    __half* w2h = (__half*)(sm + W2HI);
    __half* mh  = (__half*)(sm + MHI);
    float* rs   = (float*)(sm + RSO);
    float* ds   = (float*)(sm + DSO);
    float* ems  = (float*)(sm + EMO);
    float* b2s  = (float*)(sm + B2O);
    float* w3s  = (float*)(sm + W3O);
    float* part = (float*)(sm + PARTO);
    float* pxy  = (float*)(sm + PXYO);

    int tid = threadIdx.x;
    int wid = tid >> 5;
    int lane = tid & 31;
    int mw  = wid >> 2;
    int nw  = wid & 3;
    int cp  = (tid & 63) << 1;     // channel pair
    int jg6 = tid >> 6;            // 0..5, 16 j each
    float* mystg = (float*)(sm + STGO) + wid * (16*LDS_STG);

    load_w_tile2(w2h, s_W2h + (size_t)widx*128*128, tid, 384);
    if (tid < 128){
        b2s[tid] = b2[tid];
        w3s[tid] = COORD ? w3[tid] : 0.f;
    }
    float w0a = W1[(2*HD)  *HD + cp],  w0b = W1[(2*HD)  *HD + cp + 1];
    float w1a = W1[(2*HD+1)*HD + cp],  w1b = W1[(2*HD+1)*HD + cp + 1];

    for (int bi = blockIdx.x; bi < BN; bi += gridDim.x){
        int b = bi / NN;
        __syncthreads();

        if (tid < NN){
            rs[tid]  = g_rad[bi*NN + tid];
            ds[tid]  = g_d0 [bi*NN + tid];
            ems[tid] = em[(size_t)bi*NN + tid];
        }
        float hi0 = g_Hi[bi*HD + cp];
        float hi1 = g_Hi[bi*HD + cp + 1];
        __syncthreads();

        // ---- stage 1: channel-pair, half2 Hj load, packed silu ----
        {
            const __half2* Hjb = reinterpret_cast<const __half2*>(g_Hj16 + (size_t)b*NN*HD) + (cp >> 1);
            int j0 = jg6 * 16;
            #pragma unroll 4
            for (int jj=0; jj<16; jj++){
                int j = j0 + jj;
                half2 hj = Hjb[j*(HD/2)];
                float a0 = hi0 + __low2float(hj)  + rs[j]*w0a + ds[j]*w1a;
                float a1 = hi1 + __high2float(hj) + rs[j]*w0b + ds[j]*w1b;
                half2 sv = silu_h2(__floats2half2_rn(a0, a1));
                *reinterpret_cast<half2*>(mh + j*LDAB + cp) = sv;
            }
        }
        __syncthreads();

        // ---- MMA (single fp16 pass) + fused per-warp epilogue ----
        int rw = mw*32, cw = nw*32;
        float rowacc0 = 0.f, rowacc1 = 0.f;
        #pragma unroll
        for (int ni=0; ni<2; ni++){
            wmma::fragment<wmma::accumulator,16,16,16,float> acc[2];
            wmma::fill_fragment(acc[0], 0.f);
            wmma::fill_fragment(acc[1], 0.f);
            #pragma unroll
            for (int s=0; s<8; s++){
                wmma::fragment<wmma::matrix_a,16,16,16,__half,wmma::row_major> fa0, fa1;
                wmma::fragment<wmma::matrix_b,16,16,16,__half,wmma::row_major> fbh;
                wmma::load_matrix_sync(fa0, mh + (rw     )*LDAB + s*16, LDAB);
                wmma::load_matrix_sync(fa1, mh + (rw + 16)*LDAB + s*16, LDAB);
                wmma::load_matrix_sync(fbh, w2h + s*16*LDAB + cw + ni*16, LDAB);
                wmma::mma_sync(acc[0], fa0, fbh, acc[0]);
                wmma::mma_sync(acc[1], fa1, fbh, acc[1]);
            }
            if (COORD == 0){
                float cacc = 0.f;
                #pragma unroll
                for (int mi=0; mi<2; mi++){
                    wmma::store_matrix_sync(mystg, acc[mi], LDS_STG, wmma::mem_row_major);
                    __syncwarp();
                    int cl = lane & 15, rh = lane >> 4;
                    float p = 0.f;
                    float bb = b2s[cw + ni*16 + cl];
                    #pragma unroll
                    for (int r8=0; r8<8; r8+=2){
                        int r = rh*8 + r8;
                        float v0 = mystg[(r  )*LDS_STG + cl] + bb;
                        float v1 = mystg[(r+1)*LDS_STG + cl] + bb;
                        half2 sv = silu_h2(__floats2half2_rn(v0, v1));
                        p += __low2float(sv)  * ems[rw + mi*16 + r]
                           + __high2float(sv) * ems[rw + mi*16 + r + 1];
                    }
                    p += __shfl_down_sync(0xffffffffu, p, 16);
                    cacc += p;
                    __syncwarp();
                }
                if (lane < 16) part[mw*128 + cw + ni*16 + lane] = cacc;
            } else {
                #pragma unroll
                for (int mi=0; mi<2; mi++){
                    wmma::store_matrix_sync(mystg, acc[mi], LDS_STG, wmma::mem_row_major);
                    __syncwarp();
                    int rl = lane & 15, ch = lane >> 4;
                    float p = 0.f;
                    #pragma unroll
                    for (int c8=0; c8<8; c8+=2){
                        int cc = cw + ni*16 + ch*8 + c8;
                        float v0 = mystg[rl*LDS_STG + ch*8 + c8    ] + b2s[cc];
                        float v1 = mystg[rl*LDS_STG + ch*8 + c8 + 1] + b2s[cc+1];
                        half2 sv = silu_h2(__floats2half2_rn(v0, v1));
                        p += __low2float(sv)*w3s[cc] + __high2float(sv)*w3s[cc+1];
                    }
                    p += __shfl_down_sync(0xffffffffu, p, 16);
                    if (mi == 0) rowacc0 += p; else rowacc1 += p;
                    __syncwarp();
                }
            }
        }
        if (COORD == 1 && lane < 16){
            part[nw*96 + rw + lane]      = rowacc0;
            part[nw*96 + rw + 16 + lane] = rowacc1;
        }
        __syncthreads();

        if (COORD == 0){
            if (tid < 128)
                g_agg[bi*HD + tid] = (part[tid] + part[128+tid] + part[256+tid]) * 0.01f;
        } else {
            float v0=0.f, v1=0.f, v2=0.f;
            if (tid < NN){
                float s = part[tid] + part[96+tid] + part[192+tid] + part[288+tid];
                float sc = s * ems[tid];
                int eo = (bi*NN + tid)*3;
                v0 = g_cd[eo+0]*sc; v1 = g_cd[eo+1]*sc; v2 = g_cd[eo+2]*sc;
            }
            #pragma unroll
            for (int off=16; off>0; off>>=1){
                v0 += __shfl_down_sync(0xffffffffu, v0, off);
                v1 += __shfl_down_sync(0xffffffffu, v1, off);
                v2 += __shfl_down_sync(0xffffffffu, v2, off);
            }
            if (tid < NN && lane == 0){
                pxy[wid*4+0] = v0; pxy[wid*4+1] = v1; pxy[wid*4+2] = v2;
            }
            __syncthreads();
            if (tid < 3){
                float tot = pxy[tid] + pxy[4+tid] + pxy[8+tid];
                g_x[bi*3 + tid] = (g_x[bi*3 + tid] + tot*0.01f) * nm[bi];
            }
        }
    }
}

// ---------------- output head ----------------
__global__ void k_out(const float* __restrict__ nm, const float* __restrict__ W_out,
                      const float* __restrict__ b_out, float* __restrict__ out){
    int b = blockIdx.x;
    int n = threadIdx.x;
    int node = b*NN + n;
    float mask = nm[node];
    float vx = (g_x[node*3+0] - g_x0[node*3+0]) * mask;
    float vy = (g_x[node*3+1] - g_x0[node*3+1]) * mask;
    float vz = (g_x[node*3+2] - g_x0[node*3+2]) * mask;
    float r0 = mask, r1 = vx, r2 = vy, r3 = vz;
    #pragma unroll
    for (int off=16; off>0; off>>=1){
        r0 += __shfl_down_sync(0xffffffffu, r0, off);
        r1 += __shfl_down_sync(0xffffffffu, r1, off);
        r2 += __shfl_down_sync(0xffffffffu, r2, off);
        r3 += __shfl_down_sync(0xffffffffu, r3, off);
    }
    __shared__ float part[3][4];
    int w = n >> 5;
    if ((n & 31) == 0){ part[w][0]=r0; part[w][1]=r1; part[w][2]=r2; part[w][3]=r3; }
    __syncthreads();
    float n_per = part[0][0] + part[1][0] + part[2][0];
    float sx    = part[0][1] + part[1][1] + part[2][1];
    float sy    = part[0][2] + part[1][2] + part[2][2];
    float sz    = part[0][3] + part[1][3] + part[2][3];
    float inv = 1.0f / n_per;
    out[node*9+0] = vx - sx*inv*mask;
    out[node*9+1] = vy - sy*inv*mask;
    out[node*9+2] = vz - sz*inv*mask;
    float acc[6];
    #pragma unroll
    for (int f=0; f<6; f++) acc[f] = b_out[f];
    const float* hrow = g_h + (size_t)node*HD;
    for (int k=0; k<HD; k++){
        float hv = hrow[k];
        #pragma unroll
        for (int f=0; f<6; f++) acc[f] += hv * W_out[k*7 + f];
    }
    #pragma unroll
    for (int f=0; f<6; f++) out[node*9+3+f] = acc[f] * mask;
}

// ---------------- launch ----------------
extern "C" void kernel_launch(void* const* d_in, const int* in_sizes, int n_in,
                              void* d_out, int out_size){
    (void)in_sizes; (void)n_in; (void)out_size;
    const float* xh    = (const float*)d_in[0];
    const float* t     = (const float*)d_in[1];
    const float* nm    = (const float*)d_in[2];
    const float* em    = (const float*)d_in[3];
    const float* W_emb = (const float*)d_in[4];
    const float* b_emb = (const float*)d_in[5];
    const float* gWe1  = (const float*)d_in[6];
    const float* gbe1  = (const float*)d_in[7];
    const float* gWe2  = (const float*)d_in[8];
    const float* gbe2  = (const float*)d_in[9];
    const float* gWn1  = (const float*)d_in[10];
    const float* gbn1  = (const float*)d_in[11];
    const float* gWn2  = (const float*)d_in[12];
    const float* gbn2  = (const float*)d_in[13];
    const float* eWc1  = (const float*)d_in[14];
    const float* ebc1  = (const float*)d_in[15];
    const float* eWc2  = (const float*)d_in[16];
    const float* ebc2  = (const float*)d_in[17];
    const float* eWc3  = (const float*)d_in[18];
    const float* W_out = (const float*)d_in[19];
    const float* b_out = (const float*)d_in[20];
    float* out = (float*)d_out;

    cudaFuncSetAttribute(k_edgeW<0>, cudaFuncAttributeMaxDynamicSharedMemorySize, SMEMB);
    cudaFuncSetAttribute(k_edgeW<1>, cudaFuncAttributeMaxDynamicSharedMemorySize, SMEMB);
    cudaFuncSetAttribute(k_hihjW,    cudaFuncAttributeMaxDynamicSharedMemorySize, H_SMEM);
    cudaFuncSetAttribute(k_nodeW,    cudaFuncAttributeMaxDynamicSharedMemorySize, N_SMEM);

    const int NSPLIT = N_WE1 + N_W2 + N_WN1 + N_WN2;
    k_split<<<(NSPLIT + 255)/256, 256>>>(gWe1, eWc1, gWe2, eWc2, gWn1, gWn2);
    k_init<<<BN, HD>>>(xh, t, nm, W_emb, b_emb);
    k_radial<<<BN, NN>>>(0);

    for (int l=0; l<4; l++){
        k_radial<<<BN, NN>>>(1);
        for (int s=0; s<2; s++){
            int g = l*2 + s;
            k_hihjW<<<96, 256, H_SMEM>>>(gbe1 + g*HD, g);
            k_edgeW<0><<<296, 384, SMEMB>>>(gWe1 + (size_t)g*258*HD,
                                            gbe2 + g*HD, (const float*)0, em, nm, g);
            k_nodeW<<<48, 256, N_SMEM>>>(gbn1 + g*HD, gbn2 + g*HD, nm, g);
        }
        k_hihjW<<<96, 256, H_SMEM>>>(ebc1 + l*HD, 8 + l);
        k_edgeW<1><<<296, 384, SMEMB>>>(eWc1 + (size_t)l*258*HD,
                                        ebc2 + l*HD, eWc3 + (size_t)l*HD, em, nm, 8 + l);
    }
    k_out<<<BSZ, NN>>>(nm, W_out, b_out, out);
}

// round 13
// speedup vs baseline: 1.4458x; 1.4458x over previous
#include <cuda_runtime.h>
#include <cuda_bf16.h>
#include <cuda_fp16.h>
#include <mma.h>
#include <cstdint>

using namespace nvcuda;

#define BSZ 16
#define NN  96
#define HD  128
#define BN  (BSZ*NN)

#define LDAB 136
#define LDO  132
#define LDS_STG 20

// ---- edge kernel smem layout (80.1 KB -> 2 blocks/SM) ----
#define W2HI  0
#define MHI   34816
#define STGO  60928
#define RSO   76288
#define DSO   76672
#define EMO   77056
#define B2O   77440
#define W3O   77952
#define PARTO 78464
#define PXYO  80000
#define SMEMB 80064

// ---- k_hihjW smem ----
#define H_XH  0
#define H_XL  8704
#define H_WH  17408
#define H_WL  52224
#define H_BI  87040
#define H_SMEM 95488

// ---- k_nodeW smem (sout aliases AH/AL) ----
#define N_XH  0
#define N_XL  8704
#define N_AH  17408
#define N_AL  26112
#define N_SO  17408
#define N_WH  34816
#define N_WL  69632
#define N_BI  104448
#define N_SMEM 112896

// ---------------- scratch ----------------
__device__ float g_h  [BN*HD];
__device__ float g_Hi [BN*HD];
__device__ float g_Hj [BN*HD];
__device__ float g_agg[BN*HD];
__device__ float g_x  [BN*3];
__device__ float g_x0 [BN*3];
__device__ float g_rad[BN*NN];
__device__ float g_d0 [BN*NN];
__device__ float g_cd [BN*NN*3];

// ---------------- pre-split weights ----------------
#define N_WE1 (12*256*128)
#define N_W2  (12*128*128)
#define N_WN1 (8*256*128)
#define N_WN2 (8*128*128)
__device__ __nv_bfloat16 s_We1h[N_WE1], s_We1l[N_WE1];
__device__ __half        s_W2h [N_W2];                    // single fp16 for edge GEMM
__device__ __nv_bfloat16 s_Wn1h[N_WN1], s_Wn1l[N_WN1];
__device__ __nv_bfloat16 s_Wn2h[N_WN2], s_Wn2l[N_WN2];

__device__ __forceinline__ float silu_f(float x){
    float e = __expf(-x);
    return __fdividef(x, 1.0f + e);
}
__device__ __forceinline__ half2 silu_h2(half2 x){
    half2 e = h2exp(__hneg2(x));
    half2 d = __hadd2(__float2half2_rn(1.0f), e);
    return __hmul2(x, h2rcp(d));
}
__device__ __forceinline__ void split_bf(float v, __nv_bfloat16 &h, __nv_bfloat16 &l){
    h = __float2bfloat16(v);
    l = __float2bfloat16(v - __bfloat162float(h));
}

// ---------------- one-time weight split ----------------
__global__ void k_split(const float* __restrict__ gWe1, const float* __restrict__ eWc1,
                        const float* __restrict__ gWe2, const float* __restrict__ eWc2,
                        const float* __restrict__ gWn1, const float* __restrict__ gWn2){
    int idx = blockIdx.x*blockDim.x + threadIdx.x;
    const int T0 = N_WE1, T1 = T0 + N_W2, T2 = T1 + N_WN1, T3 = T2 + N_WN2;
    if (idx >= T3) return;
    if (idx < T0){
        int g = idx / (256*128), rem = idx % (256*128);
        float v = (g < 8) ? gWe1[(size_t)g*258*128 + rem] : eWc1[(size_t)(g-8)*258*128 + rem];
        __nv_bfloat16 h, l; split_bf(v, h, l); s_We1h[idx] = h; s_We1l[idx] = l;
    } else if (idx < T1){
        int i = idx - T0;
        int g = i / (128*128), rem = i % (128*128);
        float v = (g < 8) ? gWe2[(size_t)g*128*128 + rem] : eWc2[(size_t)(g-8)*128*128 + rem];
        s_W2h[i] = __float2half_rn(v);
    } else if (idx < T2){
        int i = idx - T1;
        __nv_bfloat16 h, l; split_bf(gWn1[i], h, l); s_Wn1h[i] = h; s_Wn1l[i] = l;
    } else {
        int i = idx - T2;
        __nv_bfloat16 h, l; split_bf(gWn2[i], h, l); s_Wn2h[i] = h; s_Wn2l[i] = l;
    }
}

// ---------------- init ----------------
__global__ void k_init(const float* __restrict__ xh, const float* __restrict__ t,
                       const float* __restrict__ nm, const float* __restrict__ W_emb,
                       const float* __restrict__ b_emb){
    int n = blockIdx.x; int c = threadIdx.x;
    __shared__ float fs[8];
    float mask = nm[n];
    if (c < 6) fs[c] = xh[n*9 + 3 + c] * mask;
    if (c == 6) fs[6] = t[0];
    if (c < 3){ float v = xh[n*9 + c] * mask; g_x0[n*3+c] = v; g_x[n*3+c] = v; }
    __syncthreads();
    float a = b_emb[c];
    #pragma unroll
    for (int f=0; f<7; f++) a += fs[f] * W_emb[f*HD + c];
    g_h[n*HD + c] = a;
}

// ---------------- radial: rad + cd from g_x; optionally also d0 (layer 0: x==x0) ----------------
__global__ void k_radial(int writeD0){
    int bi = blockIdx.x; int j = threadIdx.x;
    int b = bi / NN;
    float xi0 = g_x[bi*3+0], xi1 = g_x[bi*3+1], xi2 = g_x[bi*3+2];
    int nj = b*NN + j;
    float dx = xi0 - g_x[nj*3+0];
    float dy = xi1 - g_x[nj*3+1];
    float dz = xi2 - g_x[nj*3+2];
    float r = dx*dx + dy*dy + dz*dz;
    g_rad[bi*NN + j] = r;
    if (writeD0) g_d0[bi*NN + j] = r;
    float inv = rsqrtf(r + 1e-8f);
    int e = (bi*NN + j)*3;
    g_cd[e+0] = dx*inv; g_cd[e+1] = dy*inv; g_cd[e+2] = dz*inv;
}

// copy a 128x128 2-byte matrix into padded smem, vectorized
__device__ __forceinline__ void load_w_tile2(void* dst, const void* src, int tid, int nthr){
    const uint4* s = (const uint4*)src;
    char* d = (char*)dst;
    for (int i = tid; i < 128*128/8; i += nthr){
        int r = i >> 4, c8 = i & 15;
        *reinterpret_cast<uint4*>(d + (r*LDAB + c8*8)*2) = s[i];
    }
}

// ---------------- Hi/Hj via WMMA (bf16 hi/lo, 3-pass) ----------------
__global__ void __launch_bounds__(256,2) k_hihjW(const float* __restrict__ b1, int g){
    extern __shared__ char sm[];
    __nv_bfloat16* xh = (__nv_bfloat16*)(sm + H_XH);
    __nv_bfloat16* xl = (__nv_bfloat16*)(sm + H_XL);
    __nv_bfloat16* wh = (__nv_bfloat16*)(sm + H_WH);
    __nv_bfloat16* wl = (__nv_bfloat16*)(sm + H_WL);
    float* bias = (float*)(sm + H_BI);

    int tid = threadIdx.x;
    int wid = tid >> 5;
    int mw  = wid >> 2;
    int nw  = wid & 3;
    int half_  = blockIdx.x & 1;
    int rows0 = (blockIdx.x >> 1) * 32;

    for (int idx = tid; idx < 32*128; idx += 256){
        int r = idx >> 7, k = idx & 127;
        __nv_bfloat16 h16, l16; split_bf(g_h[(rows0+r)*HD + k], h16, l16);
        xh[r*LDAB + k] = h16; xl[r*LDAB + k] = l16;
    }
    load_w_tile2(wh, s_We1h + ((size_t)g*256 + half_*128)*128, tid, 256);
    load_w_tile2(wl, s_We1l + ((size_t)g*256 + half_*128)*128, tid, 256);
    for (int idx = tid; idx < 16*132; idx += 256){
        int cc = idx % 132;
        bias[idx] = (half_ == 0 && cc < 128) ? b1[cc] : 0.f;
    }
    __syncthreads();

    wmma::fragment<wmma::accumulator,16,16,16,float> acc[2];
    #pragma unroll
    for (int ni=0; ni<2; ni++)
        wmma::load_matrix_sync(acc[ni], bias + nw*32 + ni*16, 132, wmma::mem_row_major);
    #pragma unroll
    for (int s=0; s<8; s++){
        wmma::fragment<wmma::matrix_a,16,16,16,__nv_bfloat16,wmma::row_major> fah, fal;
        wmma::fragment<wmma::matrix_b,16,16,16,__nv_bfloat16,wmma::row_major> fbh[2], fbl[2];
        wmma::load_matrix_sync(fah, xh + (mw*16)*LDAB + s*16, LDAB);
        wmma::load_matrix_sync(fal, xl + (mw*16)*LDAB + s*16, LDAB);
        #pragma unroll
        for (int ni=0; ni<2; ni++){
            wmma::load_matrix_sync(fbh[ni], wh + s*16*LDAB + nw*32 + ni*16, LDAB);
            wmma::load_matrix_sync(fbl[ni], wl + s*16*LDAB + nw*32 + ni*16, LDAB);
        }
        #pragma unroll
        for (int ni=0; ni<2; ni++){
            wmma::mma_sync(acc[ni], fah, fbh[ni], acc[ni]);
            wmma::mma_sync(acc[ni], fah, fbl[ni], acc[ni]);
            wmma::mma_sync(acc[ni], fal, fbh[ni], acc[ni]);
        }
    }
    float* dstbase = half_ ? g_Hj : g_Hi;
    #pragma unroll
    for (int ni=0; ni<2; ni++)
        wmma::store_matrix_sync(dstbase + (size_t)(rows0 + mw*16)*HD + nw*32 + ni*16,
                                acc[ni], HD, wmma::mem_row_major);
}

// ---------------- node MLP via WMMA (sout aliases AH/AL) ----------------
__global__ void __launch_bounds__(256,2) k_nodeW(const float* __restrict__ bn1,
                       const float* __restrict__ bn2, const float* __restrict__ nm, int g){
    extern __shared__ char sm[];
    __nv_bfloat16* xh = (__nv_bfloat16*)(sm + N_XH);
    __nv_bfloat16* xl = (__nv_bfloat16*)(sm + N_XL);
    __nv_bfloat16* ah_ = (__nv_bfloat16*)(sm + N_AH);
    __nv_bfloat16* al_ = (__nv_bfloat16*)(sm + N_AL);
    __nv_bfloat16* wh = (__nv_bfloat16*)(sm + N_WH);
    __nv_bfloat16* wl = (__nv_bfloat16*)(sm + N_WL);
    float* sout = (float*)(sm + N_SO);
    float* bias = (float*)(sm + N_BI);

    int tid = threadIdx.x;
    int wid = tid >> 5;
    int mw  = wid >> 2;
    int nw  = wid & 3;
    int rows0 = blockIdx.x * 32;

    for (int idx = tid; idx < 32*128; idx += 256){
        int r = idx >> 7, k = idx & 127;
        __nv_bfloat16 h16, l16;
        split_bf(g_h[(rows0+r)*HD + k], h16, l16);
        xh[r*LDAB + k] = h16; xl[r*LDAB + k] = l16;
        split_bf(g_agg[(rows0+r)*HD + k], h16, l16);
        ah_[r*LDAB + k] = h16; al_[r*LDAB + k] = l16;
    }
    load_w_tile2(wh, s_Wn1h + (size_t)g*256*128, tid, 256);
    load_w_tile2(wl, s_Wn1l + (size_t)g*256*128, tid, 256);
    for (int idx = tid; idx < 16*132; idx += 256){
        int cc = idx % 132;
        bias[idx] = (cc < 128) ? bn1[cc] : 0.f;
    }
    __syncthreads();

    wmma::fragment<wmma::accumulator,16,16,16,float> acc[2];
    #pragma unroll
    for (int ni=0; ni<2; ni++)
        wmma::load_matrix_sync(acc[ni], bias + nw*32 + ni*16, 132, wmma::mem_row_major);

    #pragma unroll
    for (int s=0; s<8; s++){
        wmma::fragment<wmma::matrix_a,16,16,16,__nv_bfloat16,wmma::row_major> fah, fal;
        wmma::fragment<wmma::matrix_b,16,16,16,__nv_bfloat16,wmma::row_major> fbh[2], fbl[2];
        wmma::load_matrix_sync(fah, xh + (mw*16)*LDAB + s*16, LDAB);
        wmma::load_matrix_sync(fal, xl + (mw*16)*LDAB + s*16, LDAB);
        #pragma unroll
        for (int ni=0; ni<2; ni++){
            wmma::load_matrix_sync(fbh[ni], wh + s*16*LDAB + nw*32 + ni*16, LDAB);
            wmma::load_matrix_sync(fbl[ni], wl + s*16*LDAB + nw*32 + ni*16, LDAB);
        }
        #pragma unroll
        for (int ni=0; ni<2; ni++){
            wmma::mma_sync(acc[ni], fah, fbh[ni], acc[ni]);
            wmma::mma_sync(acc[ni], fah, fbl[ni], acc[ni]);
            wmma::mma_sync(acc[ni], fal, fbh[ni], acc[ni]);
        }
    }
    __syncthreads();
    load_w_tile2(wh, s_Wn1h + ((size_t)g*256 + 128)*128, tid, 256);
    load_w_tile2(wl, s_Wn1l + ((size_t)g*256 + 128)*128, tid, 256);
    __syncthreads();
    #pragma unroll
    for (int s=0; s<8; s++){
        wmma::fragment<wmma::matrix_a,16,16,16,__nv_bfloat16,wmma::row_major> fah, fal;
        wmma::fragment<wmma::matrix_b,16,16,16,__nv_bfloat16,wmma::row_major> fbh[2], fbl[2];
        wmma::load_matrix_sync(fah, ah_ + (mw*16)*LDAB + s*16, LDAB);
        wmma::load_matrix_sync(fal, al_ + (mw*16)*LDAB + s*16, LDAB);
        #pragma unroll
        for (int ni=0; ni<2; ni++){
            wmma::load_matrix_sync(fbh[ni], wh + s*16*LDAB + nw*32 + ni*16, LDAB);
            wmma::load_matrix_sync(fbl[ni], wl + s*16*LDAB + nw*32 + ni*16, LDAB);
        }
        #pragma unroll
        for (int ni=0; ni<2; ni++){
            wmma::mma_sync(acc[ni], fah, fbh[ni], acc[ni]);
            wmma::mma_sync(acc[ni], fah, fbl[ni], acc[ni]);
            wmma::mma_sync(acc[ni], fal, fbh[ni], acc[ni]);
        }
    }
    __syncthreads();
    #pragma unroll
    for (int ni=0; ni<2; ni++)
        wmma::store_matrix_sync(sout + (mw*16)*LDO + nw*32 + ni*16, acc[ni], LDO, wmma::mem_row_major);
    __syncthreads();

    for (int idx = tid; idx < 32*128; idx += 256){
        int r = idx >> 7, cc = idx & 127;
        __nv_bfloat16 h16, l16; split_bf(silu_f(sout[r*LDO + cc]), h16, l16);
        xh[r*LDAB + cc] = h16; xl[r*LDAB + cc] = l16;
    }
    load_w_tile2(wh, s_Wn2h + (size_t)g*128*128, tid, 256);
    load_w_tile2(wl, s_Wn2l + (size_t)g*128*128, tid, 256);
    for (int idx = tid; idx < 16*132; idx += 256){
        int cc = idx % 132;
        bias[idx] = (cc < 128) ? bn2[cc] : 0.f;
    }
    __syncthreads();

    #pragma unroll
    for (int ni=0; ni<2; ni++)
        wmma::load_matrix_sync(acc[ni], bias + nw*32 + ni*16, 132, wmma::mem_row_major);
    #pragma unroll
    for (int s=0; s<8; s++){
        wmma::fragment<wmma::matrix_a,16,16,16,__nv_bfloat16,wmma::row_major> fah, fal;
        wmma::fragment<wmma::matrix_b,16,16,16,__nv_bfloat16,wmma::row_major> fbh[2], fbl[2];
        wmma::load_matrix_sync(fah, xh + (mw*16)*LDAB + s*16, LDAB);
        wmma::load_matrix_sync(fal, xl + (mw*16)*LDAB + s*16, LDAB);
        #pragma unroll
        for (int ni=0; ni<2; ni++){
            wmma::load_matrix_sync(fbh[ni], wh + s*16*LDAB + nw*32 + ni*16, LDAB);
            wmma::load_matrix_sync(fbl[ni], wl + s*16*LDAB + nw*32 + ni*16, LDAB);
        }
        #pragma unroll
        for (int ni=0; ni<2; ni++){
            wmma::mma_sync(acc[ni], fah, fbh[ni], acc[ni]);
            wmma::mma_sync(acc[ni], fah, fbl[ni], acc[ni]);
            wmma::mma_sync(acc[ni], fal, fbh[ni], acc[ni]);
        }
    }
    __syncthreads();
    #pragma unroll
    for (int ni=0; ni<2; ni++)
        wmma::store_matrix_sync(sout + (mw*16)*LDO + nw*32 + ni*16, acc[ni], LDO, wmma::mem_row_major);
    __syncthreads();

    for (int idx = tid; idx < 32*128; idx += 256){
        int r = idx >> 7, cc = idx & 127;
        int n = rows0 + r;
        g_h[n*HD + cc] = (g_h[n*HD + cc] + sout[r*LDO + cc]) * nm[n];
    }
}

// ---------------- WMMA edge MLP: single-fp16 W2, h2 silu, 384 thr, 2 blocks/SM ----------------
template<int COORD>
__global__ void __launch_bounds__(384,2) k_edgeW(const float* __restrict__ W1,
        const float* __restrict__ b2, const float* __restrict__ w3,
        const float* __restrict__ em, const float* __restrict__ nm, int widx){
    extern __shared__ char sm[];
    __half* w2h = (__half*)(sm + W2HI);
    __half* mh  = (__half*)(sm + MHI);
    float* rs   = (float*)(sm + RSO);
    float* ds   = (float*)(sm + DSO);
    float* ems  = (float*)(sm + EMO);
    float* b2s  = (float*)(sm + B2O);
    float* w3s  = (float*)(sm + W3O);
    float* part = (float*)(sm + PARTO);
    float* pxy  = (float*)(sm + PXYO);

    int tid = threadIdx.x;
    int wid = tid >> 5;
    int lane = tid & 31;
    int mw  = wid >> 2;
    int nw  = wid & 3;
    int c   = tid & 127;
    int jg  = tid >> 7;
    float* mystg = (float*)(sm + STGO) + wid * (16*LDS_STG);

    load_w_tile2(w2h, s_W2h + (size_t)widx*128*128, tid, 384);
    if (tid < 128){
        b2s[tid] = b2[tid];
        w3s[tid] = COORD ? w3[tid] : 0.f;
    }
    float w0 = W1[(2*HD)  *HD + c];
    float w1 = W1[(2*HD+1)*HD + c];

    for (int bi = blockIdx.x; bi < BN; bi += gridDim.x){
        int b = bi / NN;
        __syncthreads();

        if (tid < NN){
            rs[tid]  = g_rad[bi*NN + tid];
            ds[tid]  = g_d0 [bi*NN + tid];
            ems[tid] = em[(size_t)bi*NN + tid];
        }
        float hiv = g_Hi[bi*HD + c];
        __syncthreads();

        // ---- stage 1: m[j][c] = silu_h2(Hi + Hj + rad*w0 + d0*w1) -> fp16 ----
        {
            const float* Hjb = g_Hj + (size_t)b*NN*HD + c;
            int j0 = jg*32;
            #pragma unroll 4
            for (int jj=0; jj<32; jj+=2){
                int j = j0 + jj;
                float a0 = hiv + Hjb[(size_t)j*HD]     + rs[j]*w0   + ds[j]*w1;
                float a1 = hiv + Hjb[(size_t)(j+1)*HD] + rs[j+1]*w0 + ds[j+1]*w1;
                half2 sv = silu_h2(__floats2half2_rn(a0, a1));
                mh[j*LDAB + c]     = __low2half(sv);
                mh[(j+1)*LDAB + c] = __high2half(sv);
            }
        }
        __syncthreads();

        // ---- MMA (single pass) + fused per-warp epilogue ----
        int rw = mw*32, cw = nw*32;
        float rowacc0 = 0.f, rowacc1 = 0.f;
        #pragma unroll
        for (int ni=0; ni<2; ni++){
            wmma::fragment<wmma::accumulator,16,16,16,float> acc[2];
            wmma::fill_fragment(acc[0], 0.f);
            wmma::fill_fragment(acc[1], 0.f);
            #pragma unroll
            for (int s=0; s<8; s++){
                wmma::fragment<wmma::matrix_a,16,16,16,__half,wmma::row_major> fa0, fa1;
                wmma::fragment<wmma::matrix_b,16,16,16,__half,wmma::row_major> fbh;
                wmma::load_matrix_sync(fa0, mh + (rw     )*LDAB + s*16, LDAB);
                wmma::load_matrix_sync(fa1, mh + (rw + 16)*LDAB + s*16, LDAB);
                wmma::load_matrix_sync(fbh, w2h + s*16*LDAB + cw + ni*16, LDAB);
                wmma::mma_sync(acc[0], fa0, fbh, acc[0]);
                wmma::mma_sync(acc[1], fa1, fbh, acc[1]);
            }
            if (COORD == 0){
                float cacc = 0.f;
                #pragma unroll
                for (int mi=0; mi<2; mi++){
                    wmma::store_matrix_sync(mystg, acc[mi], LDS_STG, wmma::mem_row_major);
                    __syncwarp();
                    int cl = lane & 15, rh = lane >> 4;
                    float p = 0.f;
                    float bb = b2s[cw + ni*16 + cl];
                    #pragma unroll
                    for (int r8=0; r8<8; r8+=2){
                        int r = rh*8 + r8;
                        float v0 = mystg[(r  )*LDS_STG + cl] + bb;
                        float v1 = mystg[(r+1)*LDS_STG + cl] + bb;
                        half2 sv = silu_h2(__floats2half2_rn(v0, v1));
                        p += __low2float(sv)  * ems[rw + mi*16 + r]
                           + __high2float(sv) * ems[rw + mi*16 + r + 1];
                    }
                    p += __shfl_down_sync(0xffffffffu, p, 16);
                    cacc += p;
                    __syncwarp();
                }
                if (lane < 16) part[mw*128 + cw + ni*16 + lane] = cacc;
            } else {
                #pragma unroll
                for (int mi=0; mi<2; mi++){
                    wmma::store_matrix_sync(mystg, acc[mi], LDS_STG, wmma::mem_row_major);
                    __syncwarp();
                    int rl = lane & 15, ch = lane >> 4;
                    float p = 0.f;
                    #pragma unroll
                    for (int c8=0; c8<8; c8+=2){
                        int cc = cw + ni*16 + ch*8 + c8;
                        float v0 = mystg[rl*LDS_STG + ch*8 + c8    ] + b2s[cc];
                        float v1 = mystg[rl*LDS_STG + ch*8 + c8 + 1] + b2s[cc+1];
                        half2 sv = silu_h2(__floats2half2_rn(v0, v1));
                        p += __low2float(sv)*w3s[cc] + __high2float(sv)*w3s[cc+1];
                    }
                    p += __shfl_down_sync(0xffffffffu, p, 16);
                    if (mi == 0) rowacc0 += p; else rowacc1 += p;
                    __syncwarp();
                }
            }
        }
        if (COORD == 1 && lane < 16){
            part[nw*96 + rw + lane]      = rowacc0;
            part[nw*96 + rw + 16 + lane] = rowacc1;
        }
        __syncthreads();

        if (COORD == 0){
            if (tid < 128)
                g_agg[bi*HD + tid] = (part[tid] + part[128+tid] + part[256+tid]) * 0.01f;
        } else {
            float v0=0.f, v1=0.f, v2=0.f;
            if (tid < NN){
                float s = part[tid] + part[96+tid] + part[192+tid] + part[288+tid];
                float sc = s * ems[tid];
                int eo = (bi*NN + tid)*3;
                v0 = g_cd[eo+0]*sc; v1 = g_cd[eo+1]*sc; v2 = g_cd[eo+2]*sc;
            }
            #pragma unroll
            for (int off=16; off>0; off>>=1){
                v0 += __shfl_down_sync(0xffffffffu, v0, off);
                v1 += __shfl_down_sync(0xffffffffu, v1, off);
                v2 += __shfl_down_sync(0xffffffffu, v2, off);
            }
            if (tid < NN && lane == 0){
                pxy[wid*4+0] = v0; pxy[wid*4+1] = v1; pxy[wid*4+2] = v2;
            }
            __syncthreads();
            if (tid < 3){
                float tot = pxy[tid] + pxy[4+tid] + pxy[8+tid];
                g_x[bi*3 + tid] = (g_x[bi*3 + tid] + tot*0.01f) * nm[bi];
            }
        }
    }
}

// ---------------- output head ----------------
__global__ void k_out(const float* __restrict__ nm, const float* __restrict__ W_out,
                      const float* __restrict__ b_out, float* __restrict__ out){
    int b = blockIdx.x;
    int n = threadIdx.x;
    int node = b*NN + n;
    float mask = nm[node];
    float vx = (g_x[node*3+0] - g_x0[node*3+0]) * mask;
    float vy = (g_x[node*3+1] - g_x0[node*3+1]) * mask;
    float vz = (g_x[node*3+2] - g_x0[node*3+2]) * mask;
    float r0 = mask, r1 = vx, r2 = vy, r3 = vz;
    #pragma unroll
    for (int off=16; off>0; off>>=1){
        r0 += __shfl_down_sync(0xffffffffu, r0, off);
        r1 += __shfl_down_sync(0xffffffffu, r1, off);
        r2 += __shfl_down_sync(0xffffffffu, r2, off);
        r3 += __shfl_down_sync(0xffffffffu, r3, off);
    }
    __shared__ float part[3][4];
    int w = n >> 5;
    if ((n & 31) == 0){ part[w][0]=r0; part[w][1]=r1; part[w][2]=r2; part[w][3]=r3; }
    __syncthreads();
    float n_per = part[0][0] + part[1][0] + part[2][0];
    float sx    = part[0][1] + part[1][1] + part[2][1];
    float sy    = part[0][2] + part[1][2] + part[2][2];
    float sz    = part[0][3] + part[1][3] + part[2][3];
    float inv = 1.0f / n_per;
    out[node*9+0] = vx - sx*inv*mask;
    out[node*9+1] = vy - sy*inv*mask;
    out[node*9+2] = vz - sz*inv*mask;
    float acc[6];
    #pragma unroll
    for (int f=0; f<6; f++) acc[f] = b_out[f];
    const float* hrow = g_h + (size_t)node*HD;
    for (int k=0; k<HD; k++){
        float hv = hrow[k];
        #pragma unroll
        for (int f=0; f<6; f++) acc[f] += hv * W_out[k*7 + f];
    }
    #pragma unroll
    for (int f=0; f<6; f++) out[node*9+3+f] = acc[f] * mask;
}

// ---------------- launch ----------------
extern "C" void kernel_launch(void* const* d_in, const int* in_sizes, int n_in,
                              void* d_out, int out_size){
    (void)in_sizes; (void)n_in; (void)out_size;
    const float* xh    = (const float*)d_in[0];
    const float* t     = (const float*)d_in[1];
    const float* nm    = (const float*)d_in[2];
    const float* em    = (const float*)d_in[3];
    const float* W_emb = (const float*)d_in[4];
    const float* b_emb = (const float*)d_in[5];
    const float* gWe1  = (const float*)d_in[6];
    const float* gbe1  = (const float*)d_in[7];
    const float* gWe2  = (const float*)d_in[8];
    const float* gbe2  = (const float*)d_in[9];
    const float* gWn1  = (const float*)d_in[10];
    const float* gbn1  = (const float*)d_in[11];
    const float* gWn2  = (const float*)d_in[12];
    const float* gbn2  = (const float*)d_in[13];
    const float* eWc1  = (const float*)d_in[14];
    const float* ebc1  = (const float*)d_in[15];
    const float* eWc2  = (const float*)d_in[16];
    const float* ebc2  = (const float*)d_in[17];
    const float* eWc3  = (const float*)d_in[18];
    const float* W_out = (const float*)d_in[19];
    const float* b_out = (const float*)d_in[20];
    float* out = (float*)d_out;

    cudaFuncSetAttribute(k_edgeW<0>, cudaFuncAttributeMaxDynamicSharedMemorySize, SMEMB);
    cudaFuncSetAttribute(k_edgeW<1>, cudaFuncAttributeMaxDynamicSharedMemorySize, SMEMB);
    cudaFuncSetAttribute(k_hihjW,    cudaFuncAttributeMaxDynamicSharedMemorySize, H_SMEM);
    cudaFuncSetAttribute(k_nodeW,    cudaFuncAttributeMaxDynamicSharedMemorySize, N_SMEM);

    const int NSPLIT = N_WE1 + N_W2 + N_WN1 + N_WN2;
    k_split<<<(NSPLIT + 255)/256, 256>>>(gWe1, eWc1, gWe2, eWc2, gWn1, gWn2);
    k_init<<<BN, HD>>>(xh, t, nm, W_emb, b_emb);

    for (int l=0; l<4; l++){
        k_radial<<<BN, NN>>>(l == 0 ? 1 : 0);   // layer 0: x==x0, also writes d0
        for (int s=0; s<2; s++){
            int g = l*2 + s;
            k_hihjW<<<96, 256, H_SMEM>>>(gbe1 + g*HD, g);
            k_edgeW<0><<<296, 384, SMEMB>>>(gWe1 + (size_t)g*258*HD,
                                            gbe2 + g*HD, (const float*)0, em, nm, g);
            k_nodeW<<<48, 256, N_SMEM>>>(gbn1 + g*HD, gbn2 + g*HD, nm, g);
        }
        k_hihjW<<<96, 256, H_SMEM>>>(ebc1 + l*HD, 8 + l);
        k_edgeW<1><<<296, 384, SMEMB>>>(eWc1 + (size_t)l*258*HD,
                                        ebc2 + l*HD, eWc3 + (size_t)l*HD, em, nm, 8 + l);
    }
    k_out<<<BSZ, NN>>>(nm, W_out, b_out, out);
}

// round 14
// speedup vs baseline: 1.6110x; 1.1142x over previous
#include <cuda_runtime.h>
#include <cuda_bf16.h>
#include <cuda_fp16.h>
#include <mma.h>
#include <cstdint>

using namespace nvcuda;

#define BSZ 16
#define NN  96
#define HD  128
#define BN  (BSZ*NN)

#define LDAB 136
#define LDO  132
#define LDS_STG 20

// ---- edge kernel smem layout (80.1 KB -> 2 blocks/SM) ----
#define W2HI  0
#define MHI   34816
#define STGO  60928
#define RSO   76288
#define DSO   76672
#define EMO   77056
#define B2O   77440
#define W3O   77952
#define PARTO 78464
#define PXYO  80000
#define SMEMB 80064

// ---- k_hihjW smem (x tiles + bias only; W fragments from global) ----
#define H_XH  0            // 16*136*2 = 4352
#define H_XL  4352
#define H_BI  8704         // 16*132*4 = 8448
#define H_SMEM 17152

// ---- k_nodeW smem ----
#define N_XH  0            // 4352
#define N_XL  4352
#define N_AH  8704
#define N_AL  13056
#define N_SO  17408        // 16*132*4 = 8448
#define N_BI  25856        // 8448
#define N_SMEM 34304

// ---------------- scratch ----------------
__device__ float g_h  [BN*HD];
__device__ float g_Hi [BN*HD];
__device__ float g_Hj [BN*HD];
__device__ float g_agg[BN*HD];
__device__ float g_x  [BN*3];
__device__ float g_x0 [BN*3];
__device__ float g_rad[BN*NN];
__device__ float g_d0 [BN*NN];
__device__ float g_cd [BN*NN*3];

// ---------------- pre-split weights ----------------
#define N_WE1 (12*256*128)
#define N_W2  (12*128*128)
#define N_WN1 (8*256*128)
#define N_WN2 (8*128*128)
__device__ __nv_bfloat16 s_We1h[N_WE1], s_We1l[N_WE1];
__device__ __half        s_W2h [N_W2];
__device__ __nv_bfloat16 s_Wn1h[N_WN1], s_Wn1l[N_WN1];
__device__ __nv_bfloat16 s_Wn2h[N_WN2], s_Wn2l[N_WN2];

__device__ __forceinline__ float silu_f(float x){
    float e = __expf(-x);
    return __fdividef(x, 1.0f + e);
}
__device__ __forceinline__ half2 silu_h2(half2 x){
    half2 e = h2exp(__hneg2(x));
    half2 d = __hadd2(__float2half2_rn(1.0f), e);
    return __hmul2(x, h2rcp(d));
}
__device__ __forceinline__ void split_bf(float v, __nv_bfloat16 &h, __nv_bfloat16 &l){
    h = __float2bfloat16(v);
    l = __float2bfloat16(v - __bfloat162float(h));
}

// ---------------- one-time weight split ----------------
__global__ void k_split(const float* __restrict__ gWe1, const float* __restrict__ eWc1,
                        const float* __restrict__ gWe2, const float* __restrict__ eWc2,
                        const float* __restrict__ gWn1, const float* __restrict__ gWn2){
    int idx = blockIdx.x*blockDim.x + threadIdx.x;
    const int T0 = N_WE1, T1 = T0 + N_W2, T2 = T1 + N_WN1, T3 = T2 + N_WN2;
    if (idx >= T3) return;
    if (idx < T0){
        int g = idx / (256*128), rem = idx % (256*128);
        float v = (g < 8) ? gWe1[(size_t)g*258*128 + rem] : eWc1[(size_t)(g-8)*258*128 + rem];
        __nv_bfloat16 h, l; split_bf(v, h, l); s_We1h[idx] = h; s_We1l[idx] = l;
    } else if (idx < T1){
        int i = idx - T0;
        int g = i / (128*128), rem = i % (128*128);
        float v = (g < 8) ? gWe2[(size_t)g*128*128 + rem] : eWc2[(size_t)(g-8)*128*128 + rem];
        s_W2h[i] = __float2half_rn(v);
    } else if (idx < T2){
        int i = idx - T1;
        __nv_bfloat16 h, l; split_bf(gWn1[i], h, l); s_Wn1h[i] = h; s_Wn1l[i] = l;
    } else {
        int i = idx - T2;
        __nv_bfloat16 h, l; split_bf(gWn2[i], h, l); s_Wn2h[i] = h; s_Wn2l[i] = l;
    }
}

// ---------------- init ----------------
__global__ void k_init(const float* __restrict__ xh, const float* __restrict__ t,
                       const float* __restrict__ nm, const float* __restrict__ W_emb,
                       const float* __restrict__ b_emb){
    int n = blockIdx.x; int c = threadIdx.x;
    __shared__ float fs[8];
    float mask = nm[n];
    if (c < 6) fs[c] = xh[n*9 + 3 + c] * mask;
    if (c == 6) fs[6] = t[0];
    if (c < 3){ float v = xh[n*9 + c] * mask; g_x0[n*3+c] = v; g_x[n*3+c] = v; }
    __syncthreads();
    float a = b_emb[c];
    #pragma unroll
    for (int f=0; f<7; f++) a += fs[f] * W_emb[f*HD + c];
    g_h[n*HD + c] = a;
}

// ---------------- radial: rad + cd from g_x; optionally also d0 (layer 0: x==x0) ----------------
__global__ void k_radial(int writeD0){
    int bi = blockIdx.x; int j = threadIdx.x;
    int b = bi / NN;
    float xi0 = g_x[bi*3+0], xi1 = g_x[bi*3+1], xi2 = g_x[bi*3+2];
    int nj = b*NN + j;
    float dx = xi0 - g_x[nj*3+0];
    float dy = xi1 - g_x[nj*3+1];
    float dz = xi2 - g_x[nj*3+2];
    float r = dx*dx + dy*dy + dz*dz;
    g_rad[bi*NN + j] = r;
    if (writeD0) g_d0[bi*NN + j] = r;
    float inv = rsqrtf(r + 1e-8f);
    int e = (bi*NN + j)*3;
    g_cd[e+0] = dx*inv; g_cd[e+1] = dy*inv; g_cd[e+2] = dz*inv;
}

// copy a 128x128 2-byte matrix into padded smem, vectorized (edge kernel only)
__device__ __forceinline__ void load_w_tile2(void* dst, const void* src, int tid, int nthr){
    const uint4* s = (const uint4*)src;
    char* d = (char*)dst;
    for (int i = tid; i < 128*128/8; i += nthr){
        int r = i >> 4, c8 = i & 15;
        *reinterpret_cast<uint4*>(d + (r*LDAB + c8*8)*2) = s[i];
    }
}

// ---------------- Hi/Hj via WMMA: 16-row x 128-col-half tiles, W frags from global ----------------
// grid = 192: blockIdx = rowtile(0..95) * 2 + half
__global__ void __launch_bounds__(256,3) k_hihjW(const float* __restrict__ b1, int g){
    extern __shared__ char sm[];
    __nv_bfloat16* xh = (__nv_bfloat16*)(sm + H_XH);
    __nv_bfloat16* xl = (__nv_bfloat16*)(sm + H_XL);
    float* bias = (float*)(sm + H_BI);

    int tid = threadIdx.x;
    int nw  = tid >> 5;          // warp 0..7 -> 16-col group
    int half_  = blockIdx.x & 1;
    int rows0 = (blockIdx.x >> 1) * 16;

    for (int idx = tid; idx < 16*128; idx += 256){
        int r = idx >> 7, k = idx & 127;
        __nv_bfloat16 h16, l16; split_bf(g_h[(rows0+r)*HD + k], h16, l16);
        xh[r*LDAB + k] = h16; xl[r*LDAB + k] = l16;
    }
    if (half_ == 0){
        for (int idx = tid; idx < 16*132; idx += 256){
            int cc = idx % 132;
            bias[idx] = (cc < 128) ? b1[cc] : 0.f;
        }
    }
    __syncthreads();

    wmma::fragment<wmma::accumulator,16,16,16,float> acc;
    if (half_ == 0) wmma::load_matrix_sync(acc, bias + nw*16, 132, wmma::mem_row_major);
    else            wmma::fill_fragment(acc, 0.f);

    const __nv_bfloat16* Wh = s_We1h + ((size_t)g*256 + half_*128)*128 + nw*16;
    const __nv_bfloat16* Wl = s_We1l + ((size_t)g*256 + half_*128)*128 + nw*16;
    #pragma unroll
    for (int s=0; s<8; s++){
        wmma::fragment<wmma::matrix_a,16,16,16,__nv_bfloat16,wmma::row_major> fah, fal;
        wmma::fragment<wmma::matrix_b,16,16,16,__nv_bfloat16,wmma::row_major> fbh, fbl;
        wmma::load_matrix_sync(fah, xh + s*16, LDAB);
        wmma::load_matrix_sync(fal, xl + s*16, LDAB);
        wmma::load_matrix_sync(fbh, Wh + s*16*128, 128);
        wmma::load_matrix_sync(fbl, Wl + s*16*128, 128);
        wmma::mma_sync(acc, fah, fbh, acc);
        wmma::mma_sync(acc, fah, fbl, acc);
        wmma::mma_sync(acc, fal, fbh, acc);
    }
    float* dstbase = half_ ? g_Hj : g_Hi;
    wmma::store_matrix_sync(dstbase + (size_t)rows0*HD + nw*16, acc, HD, wmma::mem_row_major);
}

// ---------------- node MLP via WMMA: 16-row tiles, fused 2 stages, W frags from global ----------------
__global__ void __launch_bounds__(256,3) k_nodeW(const float* __restrict__ bn1,
                       const float* __restrict__ bn2, const float* __restrict__ nm, int g){
    extern __shared__ char sm[];
    __nv_bfloat16* xh = (__nv_bfloat16*)(sm + N_XH);
    __nv_bfloat16* xl = (__nv_bfloat16*)(sm + N_XL);
    __nv_bfloat16* ah_ = (__nv_bfloat16*)(sm + N_AH);
    __nv_bfloat16* al_ = (__nv_bfloat16*)(sm + N_AL);
    float* sout = (float*)(sm + N_SO);
    float* bias = (float*)(sm + N_BI);

    int tid = threadIdx.x;
    int nw  = tid >> 5;          // warp 0..7 -> 16-col group
    int rows0 = blockIdx.x * 16;

    for (int idx = tid; idx < 16*128; idx += 256){
        int r = idx >> 7, k = idx & 127;
        __nv_bfloat16 h16, l16;
        split_bf(g_h[(rows0+r)*HD + k], h16, l16);
        xh[r*LDAB + k] = h16; xl[r*LDAB + k] = l16;
        split_bf(g_agg[(rows0+r)*HD + k], h16, l16);
        ah_[r*LDAB + k] = h16; al_[r*LDAB + k] = l16;
    }
    for (int idx = tid; idx < 16*132; idx += 256){
        int cc = idx % 132;
        bias[idx] = (cc < 128) ? bn1[cc] : 0.f;
    }
    __syncthreads();

    // ---- GEMM1: h @ Wn1[0:128] + agg @ Wn1[128:256], 16 k-steps ----
    wmma::fragment<wmma::accumulator,16,16,16,float> acc;
    wmma::load_matrix_sync(acc, bias + nw*16, 132, wmma::mem_row_major);
    const __nv_bfloat16* W1h = s_Wn1h + (size_t)g*256*128 + nw*16;
    const __nv_bfloat16* W1l = s_Wn1l + (size_t)g*256*128 + nw*16;
    #pragma unroll
    for (int s=0; s<16; s++){
        const __nv_bfloat16* ab_h = (s < 8) ? (xh + s*16) : (ah_ + (s-8)*16);
        const __nv_bfloat16* ab_l = (s < 8) ? (xl + s*16) : (al_ + (s-8)*16);
        wmma::fragment<wmma::matrix_a,16,16,16,__nv_bfloat16,wmma::row_major> fah, fal;
        wmma::fragment<wmma::matrix_b,16,16,16,__nv_bfloat16,wmma::row_major> fbh, fbl;
        wmma::load_matrix_sync(fah, ab_h, LDAB);
        wmma::load_matrix_sync(fal, ab_l, LDAB);
        wmma::load_matrix_sync(fbh, W1h + (size_t)s*16*128, 128);
        wmma::load_matrix_sync(fbl, W1l + (size_t)s*16*128, 128);
        wmma::mma_sync(acc, fah, fbh, acc);
        wmma::mma_sync(acc, fah, fbl, acc);
        wmma::mma_sync(acc, fal, fbh, acc);
    }
    wmma::store_matrix_sync(sout + nw*16, acc, LDO, wmma::mem_row_major);
    __syncthreads();

    // ---- u = silu(sout) -> xh/xl ; bias = bn2 ----
    for (int idx = tid; idx < 16*128; idx += 256){
        int r = idx >> 7, cc = idx & 127;
        __nv_bfloat16 h16, l16; split_bf(silu_f(sout[r*LDO + cc]), h16, l16);
        xh[r*LDAB + cc] = h16; xl[r*LDAB + cc] = l16;
    }
    for (int idx = tid; idx < 16*132; idx += 256){
        int cc = idx % 132;
        bias[idx] = (cc < 128) ? bn2[cc] : 0.f;
    }
    __syncthreads();

    // ---- GEMM2: u @ Wn2 ----
    wmma::load_matrix_sync(acc, bias + nw*16, 132, wmma::mem_row_major);
    const __nv_bfloat16* W2h_ = s_Wn2h + (size_t)g*128*128 + nw*16;
    const __nv_bfloat16* W2l_ = s_Wn2l + (size_t)g*128*128 + nw*16;
    #pragma unroll
    for (int s=0; s<8; s++){
        wmma::fragment<wmma::matrix_a,16,16,16,__nv_bfloat16,wmma::row_major> fah, fal;
        wmma::fragment<wmma::matrix_b,16,16,16,__nv_bfloat16,wmma::row_major> fbh, fbl;
        wmma::load_matrix_sync(fah, xh + s*16, LDAB);
        wmma::load_matrix_sync(fal, xl + s*16, LDAB);
        wmma::load_matrix_sync(fbh, W2h_ + (size_t)s*16*128, 128);
        wmma::load_matrix_sync(fbl, W2l_ + (size_t)s*16*128, 128);
        wmma::mma_sync(acc, fah, fbh, acc);
        wmma::mma_sync(acc, fah, fbl, acc);
        wmma::mma_sync(acc, fal, fbh, acc);
    }
    __syncthreads();   // silu-phase readers of sout done
    wmma::store_matrix_sync(sout + nw*16, acc, LDO, wmma::mem_row_major);
    __syncthreads();

    for (int idx = tid; idx < 16*128; idx += 256){
        int r = idx >> 7, cc = idx & 127;
        int n = rows0 + r;
        g_h[n*HD + cc] = (g_h[n*HD + cc] + sout[r*LDO + cc]) * nm[n];
    }
}

// ---------------- WMMA edge MLP: single-fp16 W2, h2 silu, 384 thr, 2 blocks/SM ----------------
template<int COORD>
__global__ void __launch_bounds__(384,2) k_edgeW(const float* __restrict__ W1,
        const float* __restrict__ b2, const float* __restrict__ w3,
        const float* __restrict__ em, const float* __restrict__ nm, int widx){
    extern __shared__ char sm[];
    __half* w2h = (__half*)(sm + W2HI);
    __half* mh  = (__half*)(sm + MHI);
    float* rs   = (float*)(sm + RSO);
    float* ds   = (float*)(sm + DSO);
    float* ems  = (float*)(sm + EMO);
    float* b2s  = (float*)(sm + B2O);
    float* w3s  = (float*)(sm + W3O);
    float* part = (float*)(sm + PARTO);
    float* pxy  = (float*)(sm + PXYO);

    int tid = threadIdx.x;
    int wid = tid >> 5;
    int lane = tid & 31;
    int mw  = wid >> 2;
    int nw  = wid & 3;
    int c   = tid & 127;
    int jg  = tid >> 7;
    float* mystg = (float*)(sm + STGO) + wid * (16*LDS_STG);

    load_w_tile2(w2h, s_W2h + (size_t)widx*128*128, tid, 384);
    if (tid < 128){
        b2s[tid] = b2[tid];
        w3s[tid] = COORD ? w3[tid] : 0.f;
    }
    float w0 = W1[(2*HD)  *HD + c];
    float w1 = W1[(2*HD+1)*HD + c];

    for (int bi = blockIdx.x; bi < BN; bi += gridDim.x){
        int b = bi / NN;
        __syncthreads();

        if (tid < NN){
            rs[tid]  = g_rad[bi*NN + tid];
            ds[tid]  = g_d0 [bi*NN + tid];
            ems[tid] = em[(size_t)bi*NN + tid];
        }
        float hiv = g_Hi[bi*HD + c];
        __syncthreads();

        // ---- stage 1: m[j][c] = silu_h2(Hi + Hj + rad*w0 + d0*w1) -> fp16 ----
        {
            const float* Hjb = g_Hj + (size_t)b*NN*HD + c;
            int j0 = jg*32;
            #pragma unroll 4
            for (int jj=0; jj<32; jj+=2){
                int j = j0 + jj;
                float a0 = hiv + Hjb[(size_t)j*HD]     + rs[j]*w0   + ds[j]*w1;
                float a1 = hiv + Hjb[(size_t)(j+1)*HD] + rs[j+1]*w0 + ds[j+1]*w1;
                half2 sv = silu_h2(__floats2half2_rn(a0, a1));
                mh[j*LDAB + c]     = __low2half(sv);
                mh[(j+1)*LDAB + c] = __high2half(sv);
            }
        }
        __syncthreads();

        // ---- MMA (single pass) + fused per-warp epilogue ----
        int rw = mw*32, cw = nw*32;
        float rowacc0 = 0.f, rowacc1 = 0.f;
        #pragma unroll
        for (int ni=0; ni<2; ni++){
            wmma::fragment<wmma::accumulator,16,16,16,float> acc[2];
            wmma::fill_fragment(acc[0], 0.f);
            wmma::fill_fragment(acc[1], 0.f);
            #pragma unroll
            for (int s=0; s<8; s++){
                wmma::fragment<wmma::matrix_a,16,16,16,__half,wmma::row_major> fa0, fa1;
                wmma::fragment<wmma::matrix_b,16,16,16,__half,wmma::row_major> fbh;
                wmma::load_matrix_sync(fa0, mh + (rw     )*LDAB + s*16, LDAB);
                wmma::load_matrix_sync(fa1, mh + (rw + 16)*LDAB + s*16, LDAB);
                wmma::load_matrix_sync(fbh, w2h + s*16*LDAB + cw + ni*16, LDAB);
                wmma::mma_sync(acc[0], fa0, fbh, acc[0]);
                wmma::mma_sync(acc[1], fa1, fbh, acc[1]);
            }
            if (COORD == 0){
                float cacc = 0.f;
                #pragma unroll
                for (int mi=0; mi<2; mi++){
                    wmma::store_matrix_sync(mystg, acc[mi], LDS_STG, wmma::mem_row_major);
                    __syncwarp();
                    int cl = lane & 15, rh = lane >> 4;
                    float p = 0.f;
                    float bb = b2s[cw + ni*16 + cl];
                    #pragma unroll
                    for (int r8=0; r8<8; r8+=2){
                        int r = rh*8 + r8;
                        float v0 = mystg[(r  )*LDS_STG + cl] + bb;
                        float v1 = mystg[(r+1)*LDS_STG + cl] + bb;
                        half2 sv = silu_h2(__floats2half2_rn(v0, v1));
                        p += __low2float(sv)  * ems[rw + mi*16 + r]
                           + __high2float(sv) * ems[rw + mi*16 + r + 1];
                    }
                    p += __shfl_down_sync(0xffffffffu, p, 16);
                    cacc += p;
                    __syncwarp();
                }
                if (lane < 16) part[mw*128 + cw + ni*16 + lane] = cacc;
            } else {
                #pragma unroll
                for (int mi=0; mi<2; mi++){
                    wmma::store_matrix_sync(mystg, acc[mi], LDS_STG, wmma::mem_row_major);
                    __syncwarp();
                    int rl = lane & 15, ch = lane >> 4;
                    float p = 0.f;
                    #pragma unroll
                    for (int c8=0; c8<8; c8+=2){
                        int cc = cw + ni*16 + ch*8 + c8;
                        float v0 = mystg[rl*LDS_STG + ch*8 + c8    ] + b2s[cc];
                        float v1 = mystg[rl*LDS_STG + ch*8 + c8 + 1] + b2s[cc+1];
                        half2 sv = silu_h2(__floats2half2_rn(v0, v1));
                        p += __low2float(sv)*w3s[cc] + __high2float(sv)*w3s[cc+1];
                    }
                    p += __shfl_down_sync(0xffffffffu, p, 16);
                    if (mi == 0) rowacc0 += p; else rowacc1 += p;
                    __syncwarp();
                }
            }
        }
        if (COORD == 1 && lane < 16){
            part[nw*96 + rw + lane]      = rowacc0;
            part[nw*96 + rw + 16 + lane] = rowacc1;
        }
        __syncthreads();

        if (COORD == 0){
            if (tid < 128)
                g_agg[bi*HD + tid] = (part[tid] + part[128+tid] + part[256+tid]) * 0.01f;
        } else {
            float v0=0.f, v1=0.f, v2=0.f;
            if (tid < NN){
                float s = part[tid] + part[96+tid] + part[192+tid] + part[288+tid];
                float sc = s * ems[tid];
                int eo = (bi*NN + tid)*3;
                v0 = g_cd[eo+0]*sc; v1 = g_cd[eo+1]*sc; v2 = g_cd[eo+2]*sc;
            }
            #pragma unroll
            for (int off=16; off>0; off>>=1){
                v0 += __shfl_down_sync(0xffffffffu, v0, off);
                v1 += __shfl_down_sync(0xffffffffu, v1, off);
                v2 += __shfl_down_sync(0xffffffffu, v2, off);
            }
            if (tid < NN && lane == 0){
                pxy[wid*4+0] = v0; pxy[wid*4+1] = v1; pxy[wid*4+2] = v2;
            }
            __syncthreads();
            if (tid < 3){
                float tot = pxy[tid] + pxy[4+tid] + pxy[8+tid];
                g_x[bi*3 + tid] = (g_x[bi*3 + tid] + tot*0.01f) * nm[bi];
            }
        }
    }
}

// ---------------- output head ----------------
__global__ void k_out(const float* __restrict__ nm, const float* __restrict__ W_out,
                      const float* __restrict__ b_out, float* __restrict__ out){
    int b = blockIdx.x;
    int n = threadIdx.x;
    int node = b*NN + n;
    float mask = nm[node];
    float vx = (g_x[node*3+0] - g_x0[node*3+0]) * mask;
    float vy = (g_x[node*3+1] - g_x0[node*3+1]) * mask;
    float vz = (g_x[node*3+2] - g_x0[node*3+2]) * mask;
    float r0 = mask, r1 = vx, r2 = vy, r3 = vz;
    #pragma unroll
    for (int off=16; off>0; off>>=1){
        r0 += __shfl_down_sync(0xffffffffu, r0, off);
        r1 += __shfl_down_sync(0xffffffffu, r1, off);
        r2 += __shfl_down_sync(0xffffffffu, r2, off);
        r3 += __shfl_down_sync(0xffffffffu, r3, off);
    }
    __shared__ float part[3][4];
    int w = n >> 5;
    if ((n & 31) == 0){ part[w][0]=r0; part[w][1]=r1; part[w][2]=r2; part[w][3]=r3; }
    __syncthreads();
    float n_per = part[0][0] + part[1][0] + part[2][0];
    float sx    = part[0][1] + part[1][1] + part[2][1];
    float sy    = part[0][2] + part[1][2] + part[2][2];
    float sz    = part[0][3] + part[1][3] + part[2][3];
    float inv = 1.0f / n_per;
    out[node*9+0] = vx - sx*inv*mask;
    out[node*9+1] = vy - sy*inv*mask;
    out[node*9+2] = vz - sz*inv*mask;
    float acc[6];
    #pragma unroll
    for (int f=0; f<6; f++) acc[f] = b_out[f];
    const float* hrow = g_h + (size_t)node*HD;
    for (int k=0; k<HD; k++){
        float hv = hrow[k];
        #pragma unroll
        for (int f=0; f<6; f++) acc[f] += hv * W_out[k*7 + f];
    }
    #pragma unroll
    for (int f=0; f<6; f++) out[node*9+3+f] = acc[f] * mask;
}

// ---------------- launch ----------------
extern "C" void kernel_launch(void* const* d_in, const int* in_sizes, int n_in,
                              void* d_out, int out_size){
    (void)in_sizes; (void)n_in; (void)out_size;
    const float* xh    = (const float*)d_in[0];
    const float* t     = (const float*)d_in[1];
    const float* nm    = (const float*)d_in[2];
    const float* em    = (const float*)d_in[3];
    const float* W_emb = (const float*)d_in[4];
    const float* b_emb = (const float*)d_in[5];
    const float* gWe1  = (const float*)d_in[6];
    const float* gbe1  = (const float*)d_in[7];
    const float* gWe2  = (const float*)d_in[8];
    const float* gbe2  = (const float*)d_in[9];
    const float* gWn1  = (const float*)d_in[10];
    const float* gbn1  = (const float*)d_in[11];
    const float* gWn2  = (const float*)d_in[12];
    const float* gbn2  = (const float*)d_in[13];
    const float* eWc1  = (const float*)d_in[14];
    const float* ebc1  = (const float*)d_in[15];
    const float* eWc2  = (const float*)d_in[16];
    const float* ebc2  = (const float*)d_in[17];
    const float* eWc3  = (const float*)d_in[18];
    const float* W_out = (const float*)d_in[19];
    const float* b_out = (const float*)d_in[20];
    float* out = (float*)d_out;

    cudaFuncSetAttribute(k_edgeW<0>, cudaFuncAttributeMaxDynamicSharedMemorySize, SMEMB);
    cudaFuncSetAttribute(k_edgeW<1>, cudaFuncAttributeMaxDynamicSharedMemorySize, SMEMB);
    cudaFuncSetAttribute(k_hihjW,    cudaFuncAttributeMaxDynamicSharedMemorySize, H_SMEM);
    cudaFuncSetAttribute(k_nodeW,    cudaFuncAttributeMaxDynamicSharedMemorySize, N_SMEM);

    const int NSPLIT = N_WE1 + N_W2 + N_WN1 + N_WN2;
    k_split<<<(NSPLIT + 255)/256, 256>>>(gWe1, eWc1, gWe2, eWc2, gWn1, gWn2);
    k_init<<<BN, HD>>>(xh, t, nm, W_emb, b_emb);

    for (int l=0; l<4; l++){
        k_radial<<<BN, NN>>>(l == 0 ? 1 : 0);   // layer 0: x==x0, also writes d0
        for (int s=0; s<2; s++){
            int g = l*2 + s;
            k_hihjW<<<192, 256, H_SMEM>>>(gbe1 + g*HD, g);
            k_edgeW<0><<<296, 384, SMEMB>>>(gWe1 + (size_t)g*258*HD,
                                            gbe2 + g*HD, (const float*)0, em, nm, g);
            k_nodeW<<<96, 256, N_SMEM>>>(gbn1 + g*HD, gbn2 + g*HD, nm, g);
        }
        k_hihjW<<<192, 256, H_SMEM>>>(ebc1 + l*HD, 8 + l);
        k_edgeW<1><<<296, 384, SMEMB>>>(eWc1 + (size_t)l*258*HD,
                                        ebc2 + l*HD, eWc3 + (size_t)l*HD, em, nm, 8 + l);
    }
    k_out<<<BSZ, NN>>>(nm, W_out, b_out, out);
}